// round 7
// baseline (speedup 1.0000x reference)
#include <cuda_runtime.h>
#include <cuda_fp16.h>
#include <cstdint>

#define HIDDEN   1024
#define NUM_HEADS 16
#define HEAD_SZ   64
#define BATCH      2
#define SEQ     2048
#define MTOT    (BATCH * SEQ)
#define QKV_N   (3 * HIDDEN)

// Scratch (allocation-free rule: __device__ globals), fp16
__device__ __half g_qkv[(size_t)MTOT * QKV_N];                                // 24 MB
__device__ __half g_av [(size_t)MTOT * HIDDEN];                               // 8 MB
__device__ __half g_wt [(size_t)QKV_N * HIDDEN + (size_t)HIDDEN * HIDDEN];    // 10 MB

// ---------------- helpers ----------------
__device__ __forceinline__ uint32_t smem_u32(const void* p) {
    uint32_t a;
    asm("{ .reg .u64 t; cvta.to.shared.u64 t, %1; cvt.u32.u64 %0, t; }" : "=r"(a) : "l"(p));
    return a;
}
__device__ __forceinline__ uint32_t pack2(float lo, float hi) {
    __half2 h = __floats2half2_rn(lo, hi);
    return *(uint32_t*)&h;
}
__device__ __forceinline__ void mma_f16(float c[4],
    uint32_t a0, uint32_t a1, uint32_t a2, uint32_t a3, uint32_t b0, uint32_t b1)
{
    asm volatile(
        "mma.sync.aligned.m16n8k16.row.col.f32.f16.f16.f32 "
        "{%0,%1,%2,%3}, {%4,%5,%6,%7}, {%8,%9}, {%0,%1,%2,%3};\n"
        : "+f"(c[0]), "+f"(c[1]), "+f"(c[2]), "+f"(c[3])
        : "r"(a0), "r"(a1), "r"(a2), "r"(a3), "r"(b0), "r"(b1));
}
#define LDSM4(r0, r1, r2, r3, addr) \
    asm volatile("ldmatrix.sync.aligned.m8n8.x4.shared.b16 {%0,%1,%2,%3}, [%4];" \
        : "=r"(r0), "=r"(r1), "=r"(r2), "=r"(r3) : "r"(addr))
#define LDSM4T(r0, r1, r2, r3, addr) \
    asm volatile("ldmatrix.sync.aligned.m8n8.x4.trans.shared.b16 {%0,%1,%2,%3}, [%4];" \
        : "=r"(r0), "=r"(r1), "=r"(r2), "=r"(r3) : "r"(addr))

// ---------------- transpose W[R][C] (fp32) -> T[C][R] (fp16) ----------------
__global__ __launch_bounds__(256) void transpose_h(
    const float* __restrict__ W, __half* __restrict__ T, int R, int C)
{
    __shared__ float t[32][33];
    const int tx = threadIdx.x & 31, ty = threadIdx.x >> 5;
    const int c0 = blockIdx.x * 32, r0 = blockIdx.y * 32;
#pragma unroll
    for (int j = 0; j < 4; j++)
        t[ty + 8 * j][tx] = W[(size_t)(r0 + ty + 8 * j) * C + c0 + tx];
    __syncthreads();
#pragma unroll
    for (int j = 0; j < 4; j++)
        T[(size_t)(c0 + ty + 8 * j) * R + r0 + tx] = __float2half(t[tx][ty + 8 * j]);
}

// ---------------- fp16 GEMM: C[M,N] = A[M,K] @ BT[N,K]^T + bias ----------------
// Block 128x128, BK=32, 8 warps (2x4), warp tile 64x32, ldmatrix fragments.
// Smem pitch 40 halves (80B): 16B-aligned rows, conflict-free ldmatrix.
template<bool AH, bool CH>
__global__ __launch_bounds__(256) void gemm_h(
    const void* __restrict__ Ap, const __half* __restrict__ BT,
    const float* __restrict__ bias, void* __restrict__ Cp,
    int M, int N, int K)
{
    __shared__ __half As[128][40];
    __shared__ __half Bs[128][40];

    const int tid = threadIdx.x, warp = tid >> 5, lane = tid & 31;
    const int wm = warp >> 2, wn = warp & 3;
    const int g = lane >> 2, tig = lane & 3;
    const int row0 = blockIdx.y * 128, col0 = blockIdx.x * 128;
    const int frow = tid >> 3, kq = (tid & 7) * 4;

    const __half* Ah = (const __half*)Ap + (size_t)(row0 + frow) * K + kq;
    const float*  Af = (const float*)Ap + (size_t)(row0 + frow) * K + kq;
    const __half* Bh = BT + (size_t)(col0 + frow) * K + kq;

    float acc[4][4][4];
#pragma unroll
    for (int mt = 0; mt < 4; mt++)
#pragma unroll
        for (int nt = 0; nt < 4; nt++)
#pragma unroll
            for (int i = 0; i < 4; i++) acc[mt][nt][i] = 0.0f;

    const uint32_t aBase = smem_u32(&As[0][0]) +
        (uint32_t)((wm * 64 + (lane & 7) + ((lane >> 3) & 1) * 8) * 80 + (lane >> 4) * 16);
    const uint32_t bBase = smem_u32(&Bs[0][0]) +
        (uint32_t)((wn * 32 + (lane & 7) + (lane >> 4) * 8) * 80 + ((lane >> 3) & 1) * 16);

    uint2 aS[4], bS[4];
#pragma unroll
    for (int it = 0; it < 4; it++) {
        if (AH) aS[it] = *(const uint2*)(Ah + (size_t)(it * 32) * K);
        else {
            float4 v = *(const float4*)(Af + (size_t)(it * 32) * K);
            aS[it] = make_uint2(pack2(v.x, v.y), pack2(v.z, v.w));
        }
        bS[it] = *(const uint2*)(Bh + (size_t)(it * 32) * K);
    }

    const int nk = K >> 5;
    for (int kc = 0; kc < nk; kc++) {
#pragma unroll
        for (int it = 0; it < 4; it++) {
            *(uint2*)&As[it * 32 + frow][kq] = aS[it];
            *(uint2*)&Bs[it * 32 + frow][kq] = bS[it];
        }
        __syncthreads();
        if (kc + 1 < nk) {
            const int ko = (kc + 1) * 32;
#pragma unroll
            for (int it = 0; it < 4; it++) {
                if (AH) aS[it] = *(const uint2*)(Ah + (size_t)(it * 32) * K + ko);
                else {
                    float4 v = *(const float4*)(Af + (size_t)(it * 32) * K + ko);
                    aS[it] = make_uint2(pack2(v.x, v.y), pack2(v.z, v.w));
                }
                bS[it] = *(const uint2*)(Bh + (size_t)(it * 32) * K + ko);
            }
        }
#pragma unroll
        for (int kk = 0; kk < 2; kk++) {
            uint32_t af[4][4], bf[4][2];
#pragma unroll
            for (int mt = 0; mt < 4; mt++)
                LDSM4(af[mt][0], af[mt][1], af[mt][2], af[mt][3],
                      aBase + mt * 1280 + kk * 32);
#pragma unroll
            for (int ntp = 0; ntp < 2; ntp++)
                LDSM4(bf[2 * ntp][0], bf[2 * ntp][1], bf[2 * ntp + 1][0], bf[2 * ntp + 1][1],
                      bBase + ntp * 1280 + kk * 32);
#pragma unroll
            for (int mt = 0; mt < 4; mt++)
#pragma unroll
                for (int nt = 0; nt < 4; nt++)
                    mma_f16(acc[mt][nt], af[mt][0], af[mt][1], af[mt][2], af[mt][3],
                            bf[nt][0], bf[nt][1]);
        }
        __syncthreads();
    }

    // Epilogue: c0,c1 at (row g, cols tig*2..); c2,c3 at row g+8.
#pragma unroll
    for (int mt = 0; mt < 4; mt++) {
        const int r_lo = row0 + wm * 64 + mt * 16 + g;
        const int r_hi = r_lo + 8;
#pragma unroll
        for (int nt = 0; nt < 4; nt++) {
            const int col = col0 + wn * 32 + nt * 8 + tig * 2;
            const float b0 = bias[col], b1 = bias[col + 1];
            if (CH) {
                __half* C = (__half*)Cp;
                *(uint32_t*)(C + (size_t)r_lo * N + col) =
                    pack2(acc[mt][nt][0] + b0, acc[mt][nt][1] + b1);
                *(uint32_t*)(C + (size_t)r_hi * N + col) =
                    pack2(acc[mt][nt][2] + b0, acc[mt][nt][3] + b1);
            } else {
                float* C = (float*)Cp;
                *(float2*)(C + (size_t)r_lo * N + col) =
                    make_float2(acc[mt][nt][0] + b0, acc[mt][nt][1] + b1);
                *(float2*)(C + (size_t)r_hi * N + col) =
                    make_float2(acc[mt][nt][2] + b0, acc[mt][nt][3] + b1);
            }
        }
    }
}

// ---------------- fp16 flash attention ----------------
// Grid (SEQ/128, BATCH*NUM_HEADS), 256 threads = 8 warps; warp owns 16 q-rows.
// Ks/Vs [64][72] halves (144B pitch). Qs aliases the pool during prologue.
__global__ __launch_bounds__(256) void attn_h()
{
    __shared__ __half pool[2 * 64 * 72];
    __half* Ks = pool;                 // [64][72]
    __half* Vs = pool + 64 * 72;       // [64][72]
    __half* Qs = pool;                 // [128][72] prologue alias (exact fit)

    const int tid = threadIdx.x, warp = tid >> 5, lane = tid & 31;
    const int g = lane >> 2, tig = lane & 3;
    const int bh = blockIdx.y, b = bh >> 4, h = bh & 15;
    const int q0 = blockIdx.x * 128;

    const __half* base = g_qkv + (size_t)b * SEQ * QKV_N;
    const __half2 sc = __half2half2(__float2half(0.125f));   // 2^-3, exact

    // ---- Prologue: Q tile (scaled) into Qs ----
    {
        const int r = tid >> 4, c4 = (tid & 15) * 4;
#pragma unroll
        for (int p = 0; p < 8; p++) {
            const int row = p * 16 + r;
            uint2 v = *(const uint2*)(base + (size_t)(q0 + row) * QKV_N + h * HEAD_SZ + c4);
            __half2 h0 = __hmul2(*(__half2*)&v.x, sc);
            __half2 h1 = __hmul2(*(__half2*)&v.y, sc);
            *(uint2*)&Qs[row * 72 + c4] = make_uint2(*(uint32_t*)&h0, *(uint32_t*)&h1);
        }
    }
    __syncthreads();

    // ---- Q fragments: 4 k16-steps ----
    uint32_t qf[4][4];
    {
        const uint32_t qBase = smem_u32(Qs) +
            (uint32_t)((warp * 16 + (lane & 7) + ((lane >> 3) & 1) * 8) * 144 + (lane >> 4) * 16);
#pragma unroll
        for (int kk = 0; kk < 4; kk++)
            LDSM4(qf[kk][0], qf[kk][1], qf[kk][2], qf[kk][3], qBase + kk * 32);
    }
    __syncthreads();   // pool reused for K/V

    float o[8][4];
#pragma unroll
    for (int nd = 0; nd < 8; nd++)
#pragma unroll
        for (int i = 0; i < 4; i++) o[nd][i] = 0.0f;
    float m_lo = -1e30f, m_hi = -1e30f, l_lo = 0.0f, l_hi = 0.0f;

    const int lr = tid >> 4, lc4 = (tid & 15) * 4;
    const uint32_t kBase = smem_u32(Ks) + (uint32_t)((lane & 7) * 144 + (lane >> 3) * 16);
    const uint32_t vBase = smem_u32(Vs) +
        (uint32_t)(((lane & 7) + ((lane >> 3) & 1) * 8) * 144 + (lane >> 4) * 16);

    for (int kb = 0; kb < SEQ; kb += 64) {
        // ---- K/V tiles (64x64 halves each) ----
#pragma unroll
        for (int p = 0; p < 4; p++) {
            const int row = p * 16 + lr;
            *(uint2*)&Ks[row * 72 + lc4] =
                *(const uint2*)(base + (size_t)(kb + row) * QKV_N + HIDDEN + h * HEAD_SZ + lc4);
            *(uint2*)&Vs[row * 72 + lc4] =
                *(const uint2*)(base + (size_t)(kb + row) * QKV_N + 2 * HIDDEN + h * HEAD_SZ + lc4);
        }
        __syncthreads();

        // ---- S = Q @ K^T : 8 key-octets x 4 k16-steps ----
        float c[8][4];
#pragma unroll
        for (int nt = 0; nt < 8; nt++) {
            uint32_t bK[4][2];
#pragma unroll
            for (int j = 0; j < 2; j++)
                LDSM4(bK[2 * j][0], bK[2 * j][1], bK[2 * j + 1][0], bK[2 * j + 1][1],
                      kBase + nt * 1152 + j * 64);
            c[nt][0] = c[nt][1] = c[nt][2] = c[nt][3] = 0.0f;
#pragma unroll
            for (int kk = 0; kk < 4; kk++)
                mma_f16(c[nt], qf[kk][0], qf[kk][1], qf[kk][2], qf[kk][3],
                        bK[kk][0], bK[kk][1]);
        }

        // ---- online softmax (rows g / g+8 shared across 4-lane group) ----
        float tmx_lo = -1e30f, tmx_hi = -1e30f;
#pragma unroll
        for (int nt = 0; nt < 8; nt++) {
            tmx_lo = fmaxf(tmx_lo, fmaxf(c[nt][0], c[nt][1]));
            tmx_hi = fmaxf(tmx_hi, fmaxf(c[nt][2], c[nt][3]));
        }
        tmx_lo = fmaxf(tmx_lo, __shfl_xor_sync(0xffffffffu, tmx_lo, 1));
        tmx_lo = fmaxf(tmx_lo, __shfl_xor_sync(0xffffffffu, tmx_lo, 2));
        tmx_hi = fmaxf(tmx_hi, __shfl_xor_sync(0xffffffffu, tmx_hi, 1));
        tmx_hi = fmaxf(tmx_hi, __shfl_xor_sync(0xffffffffu, tmx_hi, 2));

        const float mn_lo = fmaxf(m_lo, tmx_lo), mn_hi = fmaxf(m_hi, tmx_hi);
        const float al_lo = __expf(m_lo - mn_lo), al_hi = __expf(m_hi - mn_hi);
        m_lo = mn_lo; m_hi = mn_hi;
        l_lo *= al_lo; l_hi *= al_hi;
#pragma unroll
        for (int nd = 0; nd < 8; nd++) {
            o[nd][0] *= al_lo; o[nd][1] *= al_lo;
            o[nd][2] *= al_hi; o[nd][3] *= al_hi;
        }

        // ---- P @ V : k16 per step; C-layout pairs ARE the A-layout pairs ----
#pragma unroll
        for (int kp = 0; kp < 4; kp++) {
            float p00 = __expf(c[2 * kp][0] - m_lo), p01 = __expf(c[2 * kp][1] - m_lo);
            float p02 = __expf(c[2 * kp][2] - m_hi), p03 = __expf(c[2 * kp][3] - m_hi);
            float p10 = __expf(c[2 * kp + 1][0] - m_lo), p11 = __expf(c[2 * kp + 1][1] - m_lo);
            float p12 = __expf(c[2 * kp + 1][2] - m_hi), p13 = __expf(c[2 * kp + 1][3] - m_hi);
            l_lo += p00 + p01 + p10 + p11;
            l_hi += p02 + p03 + p12 + p13;
            const uint32_t a0 = pack2(p00, p01), a1 = pack2(p02, p03);
            const uint32_t a2 = pack2(p10, p11), a3 = pack2(p12, p13);

            uint32_t vb[8][2];
#pragma unroll
            for (int ndp = 0; ndp < 4; ndp++)
                LDSM4T(vb[2 * ndp][0], vb[2 * ndp][1], vb[2 * ndp + 1][0], vb[2 * ndp + 1][1],
                       vBase + kp * 2304 + ndp * 32);
#pragma unroll
            for (int nd = 0; nd < 8; nd++)
                mma_f16(o[nd], a0, a1, a2, a3, vb[nd][0], vb[nd][1]);
        }
        __syncthreads();
    }

    // ---- normalize + store (fp16) ----
    l_lo += __shfl_xor_sync(0xffffffffu, l_lo, 1);
    l_lo += __shfl_xor_sync(0xffffffffu, l_lo, 2);
    l_hi += __shfl_xor_sync(0xffffffffu, l_hi, 1);
    l_hi += __shfl_xor_sync(0xffffffffu, l_hi, 2);
    const float inv_lo = 1.0f / l_lo, inv_hi = 1.0f / l_hi;

    const int r_lo = q0 + warp * 16 + g, r_hi = r_lo + 8;
    __half* avb = g_av + (size_t)b * SEQ * HIDDEN + h * HEAD_SZ;
#pragma unroll
    for (int nd = 0; nd < 8; nd++) {
        const int col = nd * 8 + tig * 2;
        *(uint32_t*)(avb + (size_t)r_lo * HIDDEN + col) =
            pack2(o[nd][0] * inv_lo, o[nd][1] * inv_lo);
        *(uint32_t*)(avb + (size_t)r_hi * HIDDEN + col) =
            pack2(o[nd][2] * inv_hi, o[nd][3] * inv_hi);
    }
}

// ---------------- launch ----------------
extern "C" void kernel_launch(void* const* d_in, const int* in_sizes, int n_in,
                              void* d_out, int out_size)
{
    const float* x     = (const float*)d_in[0];
    const float* W_qkv = (const float*)d_in[1];
    const float* b_qkv = (const float*)d_in[2];
    const float* W_o   = (const float*)d_in[3];
    const float* b_o   = (const float*)d_in[4];

    __half *qkv, *av, *wt;
    cudaGetSymbolAddress((void**)&qkv, g_qkv);
    cudaGetSymbolAddress((void**)&av, g_av);
    cudaGetSymbolAddress((void**)&wt, g_wt);
    __half* wqkvT = wt;                               // [3072][1024]
    __half* woT   = wt + (size_t)QKV_N * HIDDEN;      // [1024][1024]

    transpose_h<<<dim3(QKV_N / 32, HIDDEN / 32), 256>>>(W_qkv, wqkvT, HIDDEN, QKV_N);
    transpose_h<<<dim3(HIDDEN / 32, HIDDEN / 32), 256>>>(W_o, woT, HIDDEN, HIDDEN);

    // 1) qkv (fp16) = x @ W_qkv + b_qkv
    gemm_h<false, true><<<dim3(QKV_N / 128, MTOT / 128), 256>>>(
        x, wqkvT, b_qkv, qkv, MTOT, QKV_N, HIDDEN);

    // 2) attention -> av (fp16)
    attn_h<<<dim3(SEQ / 128, BATCH * NUM_HEADS), 256>>>();

    // 3) out (fp32) = av @ W_o + b_o
    gemm_h<true, false><<<dim3(HIDDEN / 128, MTOT / 128), 256>>>(
        av, woT, b_o, d_out, MTOT, HIDDEN, HIDDEN);
}